// round 15
// baseline (speedup 1.0000x reference)
#include <cuda_runtime.h>
#include <cuda_bf16.h>
#include <math.h>
#include <stdint.h>

#define NN 100000
#define EE 800000
#define HID 128
#define NH 4
#define DH 32
#define NBLK ((NN + 1023) / 1024)   // 98
#define NPAD 100096
#define NTILES ((NN + 127) / 128)   // 782
#define EPAD 68
#define TW (128 * EPAD)             // words per 128-row image (8704)
#define TB (TW * 4)                 // bytes per image (34816)
#define ESM_BYTES (3 * TB)          // Whi | Ahi | Alo(->Wlo) = 104448 B (2 blocks/SM)
#define XLPAD 132                   // xl prefetch row stride (floats)

// ---------------- scratch (static device globals; no allocation) ----------------
__device__ unsigned int g_Ahi[(size_t)EE * 64];   // edge feats bf16-hi pairs [e][kw]
__device__ unsigned int g_Alo[(size_t)EE * 64];
__device__ unsigned int g_hhi[(size_t)NPAD * 64]; // hidden bf16 pair images
__device__ unsigned int g_hlo[(size_t)NPAD * 64];
__device__ float g_xl[NN * HID];
__device__ float g_xr[NN * HID];
__device__ float g_h [NN * HID];
__device__ float g_score[EE * NH];                // CSR-position-indexed
__device__ unsigned int g_WhiE[8192], g_WloE[8192];
__device__ unsigned int g_WhiL[8192], g_WloL[8192];
__device__ unsigned int g_WhiR[8192], g_WloR[8192];
__device__ int g_deg[NN], g_cursor[NN], g_rowptr[NN + 1];
__device__ int g_eids[EE];                        // CSR position -> edge id
__device__ int2 g_sd[EE];                         // (src, dst) per CSR position
__device__ int g_bsum[NBLK], g_boff[NBLK];

// ---------------- helpers ----------------
__device__ __forceinline__ float fast_silu(float z) {
    return __fdividef(z, 1.0f + __expf(-z));
}
__device__ __forceinline__ unsigned int packbf2(float x, float y) {
    __nv_bfloat162 t = __floats2bfloat162_rn(x, y);
    return *(unsigned int*)&t;
}
__device__ __forceinline__ void bf_split(float x, float& hi, float& lo) {
    __nv_bfloat16 h = __float2bfloat16_rn(x);
    hi = __bfloat162float(h);
    lo = x - hi;
}
__device__ __forceinline__ void mma_bf16(float c[4],
                                         unsigned int a0, unsigned int a1,
                                         unsigned int a2, unsigned int a3,
                                         unsigned int b0, unsigned int b1) {
    asm volatile("mma.sync.aligned.m16n8k16.row.col.f32.bf16.bf16.f32 "
                 "{%0,%1,%2,%3}, {%4,%5,%6,%7}, {%8,%9}, {%0,%1,%2,%3};"
                 : "+f"(c[0]), "+f"(c[1]), "+f"(c[2]), "+f"(c[3])
                 : "r"(a0), "r"(a1), "r"(a2), "r"(a3), "r"(b0), "r"(b1));
}
__device__ __forceinline__ void ldsm4(unsigned int r[4], uint32_t addr) {
    asm volatile("ldmatrix.sync.aligned.m8n8.x4.shared.b16 {%0,%1,%2,%3}, [%4];"
                 : "=r"(r[0]), "=r"(r[1]), "=r"(r[2]), "=r"(r[3]) : "r"(addr));
}
__device__ __forceinline__ uint32_t smem_u32(const void* p) {
    uint32_t a;
    asm("{ .reg .u64 t; cvta.to.shared.u64 t, %1; cvt.u32.u64 %0, t; }" : "=r"(a) : "l"(p));
    return a;
}
__device__ __forceinline__ void cp16(uint32_t d, const void* s) {
    size_t gs = __cvta_generic_to_global((void*)s);
    asm volatile("cp.async.cg.shared.global [%0], [%1], 16;"
                 :: "r"(d), "l"((unsigned long long)gs) : "memory");
}
__device__ __forceinline__ void cp_commit() {
    asm volatile("cp.async.commit_group;" ::: "memory");
}
template <int N>
__device__ __forceinline__ void cp_wait() {
    asm volatile("cp.async.wait_group %0;" :: "n"(N) : "memory");
}

// ---------------- CSR build (by dst) ----------------
__global__ void zero_kernel() {
    int i = blockIdx.x * blockDim.x + threadIdx.x;
    if (i < NN) { g_deg[i] = 0; g_cursor[i] = 0; }
    if (i < (NPAD - NN) * 64) {
        g_hhi[(size_t)NN * 64 + i] = 0;
        g_hlo[(size_t)NN * 64 + i] = 0;
    }
}
__global__ void hist_kernel(const int* __restrict__ ei) {
    int e = blockIdx.x * blockDim.x + threadIdx.x;
    if (e < EE) atomicAdd(&g_deg[ei[EE + e]], 1);
}
__global__ void deg_block_sum() {
    __shared__ int sh[1024];
    int i = blockIdx.x * 1024 + threadIdx.x;
    sh[threadIdx.x] = (i < NN) ? g_deg[i] : 0;
    __syncthreads();
    for (int off = 512; off; off >>= 1) {
        if (threadIdx.x < off) sh[threadIdx.x] += sh[threadIdx.x + off];
        __syncthreads();
    }
    if (threadIdx.x == 0) g_bsum[blockIdx.x] = sh[0];
}
__global__ void bsum_scan() {
    __shared__ int sh[128];
    int t = threadIdx.x;
    int v = (t < NBLK) ? g_bsum[t] : 0;
    sh[t] = v;
    __syncthreads();
    for (int off = 1; off < 128; off <<= 1) {
        int u = (t >= off) ? sh[t - off] : 0;
        __syncthreads();
        sh[t] += u;
        __syncthreads();
    }
    if (t < NBLK) g_boff[t] = sh[t] - v;
}
__global__ void rowptr_kernel() {
    __shared__ int sh[1024];
    int i = blockIdx.x * 1024 + threadIdx.x;
    int v = (i < NN) ? g_deg[i] : 0;
    sh[threadIdx.x] = v;
    __syncthreads();
    for (int off = 1; off < 1024; off <<= 1) {
        int u = (threadIdx.x >= off) ? sh[threadIdx.x - off] : 0;
        __syncthreads();
        sh[threadIdx.x] += u;
        __syncthreads();
    }
    if (i < NN) g_rowptr[i + 1] = sh[threadIdx.x] + g_boff[blockIdx.x];
    if (i == 0) g_rowptr[0] = 0;
}
__global__ void scatter_kernel(const int* __restrict__ ei) {
    int e = blockIdx.x * blockDim.x + threadIdx.x;
    if (e < EE) {
        int src = ei[e];
        int d = ei[EE + e];
        int pos = g_rowptr[d] + atomicAdd(&g_cursor[d], 1);
        g_eids[pos] = e;
        g_sd[pos] = make_int2(src, d);
    }
}

// -------- edge feature projection: bf16 hi/lo images at EDGE positions ----------
__global__ void eproj_kernel(const float* __restrict__ attr,
                             const float* __restrict__ W,
                             const float* __restrict__ b) {
    int idx = blockIdx.x * blockDim.x + threadIdx.x;   // E*32 threads
    int e = idx >> 5, c4 = (idx & 31) << 2;
    float a0 = __ldg(&attr[e * 3 + 0]);
    float a1 = __ldg(&attr[e * 3 + 1]);
    float a2 = __ldg(&attr[e * 3 + 2]);
    float v[4];
#pragma unroll
    for (int u = 0; u < 4; u++) {
        int j = c4 + u;
        float z = __ldg(&b[j]);
        z = fmaf(a0, __ldg(&W[j]),           z);
        z = fmaf(a1, __ldg(&W[HID + j]),     z);
        z = fmaf(a2, __ldg(&W[2 * HID + j]), z);
        v[u] = fast_silu(z);
    }
    float h0, l0, h1, l1, h2, l2, h3, l3;
    bf_split(v[0], h0, l0); bf_split(v[1], h1, l1);
    bf_split(v[2], h2, l2); bf_split(v[3], h3, l3);
    size_t base = (size_t)e * 64 + (c4 >> 1);
    *(uint2*)&g_Ahi[base] = make_uint2(packbf2(h0, h1), packbf2(h2, h3));
    *(uint2*)&g_Alo[base] = make_uint2(packbf2(l0, l1), packbf2(l2, l3));
}

// ---------------- W image prep ----------------
__global__ void wprep_kernel(const float* __restrict__ W, int which) {
    int idx = blockIdx.x * 256 + threadIdx.x;   // 8192
    int n = idx >> 6, kw = idx & 63;
    float w0 = __ldg(&W[(2 * kw) * HID + n]);
    float w1 = __ldg(&W[(2 * kw + 1) * HID + n]);
    float h0, l0, h1, l1;
    bf_split(w0, h0, l0);
    bf_split(w1, h1, l1);
    unsigned int* hi = (which == 0) ? g_WhiE : (which == 1) ? g_WhiL : g_WhiR;
    unsigned int* lo = (which == 0) ? g_WloE : (which == 1) ? g_WloL : g_WloR;
    hi[idx] = packbf2(h0, h1);
    lo[idx] = packbf2(l0, l1);
}
__global__ void wprep3_kernel(const float* __restrict__ Wl,
                              const float* __restrict__ Wr,
                              const float* __restrict__ We) {
    int idx = blockIdx.x * 256 + threadIdx.x;   // 24576
    int which = idx >> 13, id = idx & 8191;
    const float* W = (which == 0) ? Wl : (which == 1) ? Wr : We;
    unsigned int* hi = (which == 0) ? g_WhiL : (which == 1) ? g_WhiR : g_WhiE;
    unsigned int* lo = (which == 0) ? g_WloL : (which == 1) ? g_WloR : g_WloE;
    int n = id >> 6, kw = id & 63;
    float w0 = __ldg(&W[(2 * kw) * HID + n]);
    float w1 = __ldg(&W[(2 * kw + 1) * HID + n]);
    float h0, l0, h1, l1;
    bf_split(w0, h0, l0);
    bf_split(w1, h1, l1);
    hi[id] = packbf2(h0, h1);
    lo[id] = packbf2(l0, l1);
}

// ---- one bf16 mma pass over the tile via ldmatrix (8 K-steps) ----
__device__ __forceinline__ void pass_mma(float acc[2][8][4],
                                         uint32_t aBase, uint32_t bBase,
                                         int mb, int nb, int lane) {
    uint32_t aoff = (uint32_t)(((mb + (lane & 15)) * EPAD + ((lane >> 4) << 2)) * 4);
    uint32_t boff = (uint32_t)(((nb + (lane & 7) + ((lane >> 4) << 3)) * EPAD
                                + (((lane >> 3) & 1) << 2)) * 4);
    uint32_t a0a = aBase + aoff;
    uint32_t a1a = a0a + 16 * EPAD * 4;
    uint32_t bja = bBase + boff;
#pragma unroll
    for (int ks = 0; ks < 8; ks++) {
        unsigned int a0[4], a1[4];
        ldsm4(a0, a0a + ks * 32);
        ldsm4(a1, a1a + ks * 32);
        unsigned int b[4][4];
#pragma unroll
        for (int jj = 0; jj < 4; jj++)
            ldsm4(b[jj], bja + (uint32_t)(jj * 16 * EPAD * 4) + ks * 32);
#pragma unroll
        for (int jj = 0; jj < 4; jj++) {
            mma_bf16(acc[0][2 * jj + 0], a0[0], a0[1], a0[2], a0[3], b[jj][0], b[jj][1]);
            mma_bf16(acc[0][2 * jj + 1], a0[0], a0[1], a0[2], a0[3], b[jj][2], b[jj][3]);
            mma_bf16(acc[1][2 * jj + 0], a1[0], a1[1], a1[2], a1[3], b[jj][0], b[jj][1]);
            mma_bf16(acc[1][2 * jj + 1], a1[0], a1[1], a1[2], a1[3], b[jj][2], b[jj][3]);
        }
    }
}

// ---- staging: A via eid indirection + Whi, one cp.async group ----
__device__ __forceinline__ void stage_edge(uint32_t sb, const unsigned int* gWhi,
                                           int m0, int tid) {
#pragma unroll
    for (int i = 0; i < 8; i++) {
        int idx = i * 256 + tid;
        int row = idx >> 4, c = (idx & 15) << 2;
        int eid = __ldg(&g_eids[m0 + row]);   // 16 threads/row -> broadcast
        uint32_t doff = (uint32_t)(row * EPAD + c) * 4;
        cp16(sb + TB + doff, &g_Ahi[(size_t)eid * 64 + c]);
        cp16(sb + 2 * TB + doff, &g_Alo[(size_t)eid * 64 + c]);
        cp16(sb + doff, &gWhi[(size_t)row * 64 + c]);
    }
    cp_commit();
}
__device__ __forceinline__ void stage_node(uint32_t sb, const unsigned int* gWhi,
                                           int m0, int tid) {
#pragma unroll
    for (int i = 0; i < 8; i++) {
        int idx = i * 256 + tid;
        int row = idx >> 4, c = (idx & 15) << 2;
        uint32_t doff = (uint32_t)(row * EPAD + c) * 4;
        cp16(sb + TB + doff, &g_hhi[(size_t)(m0 + row) * 64 + c]);
        cp16(sb + 2 * TB + doff, &g_hlo[(size_t)(m0 + row) * 64 + c]);
        cp16(sb + doff, &gWhi[(size_t)row * 64 + c]);
    }
    cp_commit();
}
__device__ __forceinline__ void stage_Wlo(uint32_t dst, const unsigned int* gWlo,
                                          int tid) {
#pragma unroll
    for (int i = 0; i < 8; i++) {
        int idx = i * 256 + tid;
        int row = idx >> 4, c = (idx & 15) << 2;
        cp16(dst + (uint32_t)(row * EPAD + c) * 4, &gWlo[(size_t)row * 64 + c]);
    }
    cp_commit();
}
__device__ __forceinline__ void prefetch_xl(uint32_t dstbase, int p0, int tid) {
#pragma unroll
    for (int i = 0; i < 8; i++) {
        int idx = i * 256 + tid;
        int row = idx >> 5;
        int c = (idx & 31) << 2;
        int src = __ldg(&g_sd[p0 + row].x);
        cp16(dstbase + (uint32_t)(row * XLPAD + c) * 4,
             &g_xl[(size_t)src * HID + c]);
    }
    cp_commit();
}

// ========= edge GEMM + fused score (3-image smem, 2 blocks/SM) =========
__global__ __launch_bounds__(256, 2) void gemm_edge_score_mma(
        const float* __restrict__ att) {
    extern __shared__ __align__(16) unsigned int esm[];
    uint32_t sb = smem_u32(esm);
    int tid = threadIdx.x;
    int m0 = blockIdx.x * 128;

    stage_edge(sb, g_WhiE, m0, tid);
    cp_wait<0>();
    __syncthreads();

    int wid = tid >> 5, lane = tid & 31, g = lane >> 2, q = lane & 3;
    int mb = (wid & 3) * 32;
    int nb = (wid >> 2) * 64;

    float acc[2][8][4];
#pragma unroll
    for (int t = 0; t < 2; t++)
#pragma unroll
        for (int j = 0; j < 8; j++)
#pragma unroll
            for (int c = 0; c < 4; c++) acc[t][j][c] = 0.f;

    // p0: (Alo, Whi) — Alo dead afterwards
    pass_mma(acc, sb + 2 * TB, sb, mb, nb, lane);
    __syncthreads();
    stage_Wlo(sb + 2 * TB, g_WloE, tid);            // Wlo -> Alo space

    // p1: (Ahi, Whi) — Whi dead afterwards (Wlo load overlaps)
    pass_mma(acc, sb + TB, sb, mb, nb, lane);
    __syncthreads();
    prefetch_xl(sb, m0, tid);                        // xl rows 0..63 -> Whi space
    cp_wait<1>();                                    // Wlo done
    __syncthreads();

    // p2: (Ahi, Wlo) (xl load overlaps)
    pass_mma(acc, sb + TB, sb + 2 * TB, mb, nb, lane);
    cp_wait<0>();
    __syncthreads();

    const float* xlb0 = (const float*)esm;
    float2 attv[8];
#pragma unroll
    for (int j = 0; j < 8; j++)
        attv[j] = *(const float2*)&att[nb + 8 * j + 2 * q];

#pragma unroll
    for (int t = 0; t < 2; t++) {
#pragma unroll
        for (int rr = 0; rr < 2; rr++) {
            int row = mb + 16 * t + 8 * rr + g;
            int pos = m0 + row;
            int2 sd = __ldg(&g_sd[pos]);
            const float* xlp = (row < 64) ? (xlb0 + row * XLPAD)
                                          : &g_xl[(size_t)sd.x * HID];
            const float* xrp = &g_xr[(size_t)sd.y * HID];
            float p0 = 0.f, p1 = 0.f;
#pragma unroll
            for (int j = 0; j < 8; j++) {
                int cc = nb + 8 * j + 2 * q;
                float2 xl = *(const float2*)&xlp[cc];
                float2 xr = *(const float2*)&xrp[cc];
                float e0 = acc[t][j][rr * 2 + 0] + xl.x + xr.x;
                float e1 = acc[t][j][rr * 2 + 1] + xl.y + xr.y;
                e0 = (e0 > 0.f) ? e0 : 0.2f * e0;
                e1 = (e1 > 0.f) ? e1 : 0.2f * e1;
                float ps = fmaf(e0, attv[j].x, e1 * attv[j].y);
                if (j < 4) p0 += ps; else p1 += ps;
            }
            p0 += __shfl_xor_sync(0xffffffffu, p0, 1);
            p0 += __shfl_xor_sync(0xffffffffu, p0, 2);
            p1 += __shfl_xor_sync(0xffffffffu, p1, 1);
            p1 += __shfl_xor_sync(0xffffffffu, p1, 2);
            if (q == 0)
                *(float2*)&g_score[(size_t)pos * 4 + (nb >> 5)] =
                    make_float2(p0, p1);
        }
    }
}

// ============ node GEMM (3-image smem, 2 blocks/SM) ==========
__global__ __launch_bounds__(256, 2) void gemm_node_mma(
        const float* __restrict__ bl, const float* __restrict__ br) {
    extern __shared__ __align__(16) unsigned int esm[];
    uint32_t sb = smem_u32(esm);
    int tid = threadIdx.x;
    int m0 = blockIdx.x * 128;

    const unsigned int* gWhi = blockIdx.y ? g_WhiR : g_WhiL;
    const unsigned int* gWlo = blockIdx.y ? g_WloR : g_WloL;
    const float* bias = blockIdx.y ? br : bl;
    float* C = blockIdx.y ? g_xr : g_xl;

    stage_node(sb, gWhi, m0, tid);
    cp_wait<0>();
    __syncthreads();

    int wid = tid >> 5, lane = tid & 31, g = lane >> 2, q = lane & 3;
    int mb = (wid & 3) * 32;
    int nb = (wid >> 2) * 64;

    float acc[2][8][4];
#pragma unroll
    for (int t = 0; t < 2; t++)
#pragma unroll
        for (int j = 0; j < 8; j++)
#pragma unroll
            for (int c = 0; c < 4; c++) acc[t][j][c] = 0.f;

    pass_mma(acc, sb + 2 * TB, sb, mb, nb, lane);   // (Alo, Whi)
    __syncthreads();
    stage_Wlo(sb + 2 * TB, gWlo, tid);              // Wlo -> Alo space
    pass_mma(acc, sb + TB, sb, mb, nb, lane);       // (Ahi, Whi)
    cp_wait<0>();
    __syncthreads();
    pass_mma(acc, sb + TB, sb + 2 * TB, mb, nb, lane); // (Ahi, Wlo)

    float2 biasv[8];
#pragma unroll
    for (int j = 0; j < 8; j++)
        biasv[j] = *(const float2*)&bias[nb + 8 * j + 2 * q];

#pragma unroll
    for (int t = 0; t < 2; t++) {
#pragma unroll
        for (int rr = 0; rr < 2; rr++) {
            int m = m0 + mb + 16 * t + 8 * rr + g;
            if (m < NN) {
#pragma unroll
                for (int j = 0; j < 8; j++) {
                    int cc = nb + 8 * j + 2 * q;
                    *(float2*)&C[(size_t)m * HID + cc] =
                        make_float2(acc[t][j][rr * 2 + 0] + biasv[j].x,
                                    acc[t][j][rr * 2 + 1] + biasv[j].y);
                }
            }
        }
    }
}

// ---------------- layer-0 node projection (K=12) ----------------
__global__ void node_proj12(const float* __restrict__ x,
                            const float* __restrict__ Wl, const float* __restrict__ bl,
                            const float* __restrict__ Wr, const float* __restrict__ br) {
    int idx = blockIdx.x * blockDim.x + threadIdx.x;
    int n = idx >> 7, j = idx & 127;
    float a = __ldg(&bl[j]);
    float b = __ldg(&br[j]);
#pragma unroll
    for (int k = 0; k < 12; k++) {
        float xv = __ldg(&x[n * 12 + k]);
        a = fmaf(xv, __ldg(&Wl[k * HID + j]), a);
        b = fmaf(xv, __ldg(&Wr[k * HID + j]), b);
    }
    g_xl[idx] = a;
    g_xr[idx] = b;
}

// ------- fused per-node: softmax + aggregate + bias + LN + SiLU (+res) ----------
template <bool RES, bool LAST>
__global__ void node_fused_kernel(const float* __restrict__ gat_bias,
                                  const float* __restrict__ lng,
                                  const float* __restrict__ lnb,
                                  float* __restrict__ dout) {
    int n = blockIdx.x * 4 + (threadIdx.x >> 5);
    int lane = threadIdx.x & 31;
    if (n >= NN) return;
    int s0 = g_rowptr[n];
    int s1 = g_rowptr[n + 1];

    float mx = -3.4e38f;
    for (int p = s0 * 4 + lane; p < s1 * 4; p += 32)
        mx = fmaxf(mx, g_score[p]);
    mx = fmaxf(mx, __shfl_xor_sync(0xffffffffu, mx, 4));
    mx = fmaxf(mx, __shfl_xor_sync(0xffffffffu, mx, 8));
    mx = fmaxf(mx, __shfl_xor_sync(0xffffffffu, mx, 16));

    float den = 0.f;
    for (int p = s0 * 4 + lane; p < s1 * 4; p += 32)
        den += __expf(g_score[p] - mx);
    den += __shfl_xor_sync(0xffffffffu, den, 4);
    den += __shfl_xor_sync(0xffffffffu, den, 8);
    den += __shfl_xor_sync(0xffffffffu, den, 16);
    float inv = __fdividef(1.f, den + 1e-16f);

    float acc0 = 0.f, acc1 = 0.f, acc2 = 0.f, acc3 = 0.f;
    int i = s0;
    for (; i + 1 < s1; i += 2) {     // unroll x2: two xl gathers in flight
        int srcA = g_sd[i].x;
        int srcB = g_sd[i + 1].x;
        float a = 0.f, b = 0.f;
        if (lane < 4) {
            a = __expf(g_score[(size_t)i * 4 + lane] - mx) * inv;
            b = __expf(g_score[(size_t)(i + 1) * 4 + lane] - mx) * inv;
        }
        const float* xlA = &g_xl[(size_t)srcA * HID];
        const float* xlB = &g_xl[(size_t)srcB * HID];
        float A0 = xlA[0 * DH + lane], A1 = xlA[1 * DH + lane];
        float A2 = xlA[2 * DH + lane], A3 = xlA[3 * DH + lane];
        float B0 = xlB[0 * DH + lane], B1 = xlB[1 * DH + lane];
        float B2 = xlB[2 * DH + lane], B3 = xlB[3 * DH + lane];
        acc0 = fmaf(A0, __shfl_sync(0xffffffffu, a, 0), acc0);
        acc1 = fmaf(A1, __shfl_sync(0xffffffffu, a, 1), acc1);
        acc2 = fmaf(A2, __shfl_sync(0xffffffffu, a, 2), acc2);
        acc3 = fmaf(A3, __shfl_sync(0xffffffffu, a, 3), acc3);
        acc0 = fmaf(B0, __shfl_sync(0xffffffffu, b, 0), acc0);
        acc1 = fmaf(B1, __shfl_sync(0xffffffffu, b, 1), acc1);
        acc2 = fmaf(B2, __shfl_sync(0xffffffffu, b, 2), acc2);
        acc3 = fmaf(B3, __shfl_sync(0xffffffffu, b, 3), acc3);
    }
    if (i < s1) {
        int src = g_sd[i].x;
        float a = 0.f;
        if (lane < 4) a = __expf(g_score[(size_t)i * 4 + lane] - mx) * inv;
        const float* xl = &g_xl[(size_t)src * HID];
        acc0 = fmaf(xl[0 * DH + lane], __shfl_sync(0xffffffffu, a, 0), acc0);
        acc1 = fmaf(xl[1 * DH + lane], __shfl_sync(0xffffffffu, a, 1), acc1);
        acc2 = fmaf(xl[2 * DH + lane], __shfl_sync(0xffffffffu, a, 2), acc2);
        acc3 = fmaf(xl[3 * DH + lane], __shfl_sync(0xffffffffu, a, 3), acc3);
    }

    float v0 = acc0 + __ldg(&gat_bias[0 * DH + lane]);
    float v1 = acc1 + __ldg(&gat_bias[1 * DH + lane]);
    float v2 = acc2 + __ldg(&gat_bias[2 * DH + lane]);
    float v3 = acc3 + __ldg(&gat_bias[3 * DH + lane]);

    float sm = v0 + v1 + v2 + v3;
#pragma unroll
    for (int off = 16; off; off >>= 1) sm += __shfl_xor_sync(0xffffffffu, sm, off);
    float mean = sm * (1.f / 128.f);
    float d0 = v0 - mean, d1 = v1 - mean, d2 = v2 - mean, d3 = v3 - mean;
    float sq = d0 * d0 + d1 * d1 + d2 * d2 + d3 * d3;
#pragma unroll
    for (int off = 16; off; off >>= 1) sq += __shfl_xor_sync(0xffffffffu, sq, off);
    float rstd = rsqrtf(sq * (1.f / 128.f) + 1e-5f);

#pragma unroll
    for (int h = 0; h < 4; h++) {
        int j = h * DH + lane;
        float d = (h == 0 ? d0 : h == 1 ? d1 : h == 2 ? d2 : d3);
        float t = fmaf(d * rstd, __ldg(&lng[j]), __ldg(&lnb[j]));
        float sil = fast_silu(t);
        float o = RES ? (g_h[n * HID + j] + sil) : sil;
        if (LAST) {
            dout[n * HID + j] = o;
        } else {
            g_h[n * HID + j] = o;
            float on = __shfl_down_sync(0xffffffffu, o, 1);
            if (!(lane & 1)) {
                float h0, l0, h1, l1;
                bf_split(o, h0, l0);
                bf_split(on, h1, l1);
                g_hhi[(size_t)n * 64 + (j >> 1)] = packbf2(h0, h1);
                g_hlo[(size_t)n * 64 + (j >> 1)] = packbf2(l0, l1);
            }
        }
    }
}

// ---------------- launch ----------------
extern "C" void kernel_launch(void* const* d_in, const int* in_sizes, int n_in,
                              void* d_out, int out_size) {
    const float* x     = (const float*)d_in[0];
    const int*   ei    = (const int*)  d_in[1];
    const float* eattr = (const float*)d_in[2];
    const float* epw   = (const float*)d_in[3];
    const float* epb   = (const float*)d_in[4];
    const float* l0Wl  = (const float*)d_in[5];
    const float* l0bl  = (const float*)d_in[6];
    const float* l0Wr  = (const float*)d_in[7];
    const float* l0br  = (const float*)d_in[8];
    const float* l0We  = (const float*)d_in[9];
    const float* l0att = (const float*)d_in[10];
    const float* l0bias= (const float*)d_in[11];
    const float* Wl    = (const float*)d_in[12];
    const float* bl    = (const float*)d_in[13];
    const float* Wr    = (const float*)d_in[14];
    const float* br    = (const float*)d_in[15];
    const float* We    = (const float*)d_in[16];
    const float* att   = (const float*)d_in[17];
    const float* bias  = (const float*)d_in[18];
    const float* lng   = (const float*)d_in[19];
    const float* lnb   = (const float*)d_in[20];
    float* out = (float*)d_out;

    static bool init_done = false;
    static cudaStream_t s1;
    static cudaEvent_t ev0, ev1;
    if (!init_done) {
        cudaFuncSetAttribute(gemm_edge_score_mma,
                             cudaFuncAttributeMaxDynamicSharedMemorySize, ESM_BYTES);
        cudaFuncSetAttribute(gemm_node_mma,
                             cudaFuncAttributeMaxDynamicSharedMemorySize, ESM_BYTES);
        cudaStreamCreateWithFlags(&s1, cudaStreamNonBlocking);
        cudaEventCreateWithFlags(&ev0, cudaEventDisableTiming);
        cudaEventCreateWithFlags(&ev1, cudaEventDisableTiming);
        init_done = true;
    }

    // fork: s1 runs eproj/proj/wprep concurrently with the CSR chain on s0
    cudaEventRecord(ev0, 0);
    cudaStreamWaitEvent(s1, ev0, 0);

    // s0: CSR build
    zero_kernel<<<(NN + 255) / 256, 256>>>();
    hist_kernel<<<(EE + 255) / 256, 256>>>(ei);
    deg_block_sum<<<NBLK, 1024>>>();
    bsum_scan<<<1, 128>>>();
    rowptr_kernel<<<NBLK, 1024>>>();
    scatter_kernel<<<(EE + 255) / 256, 256>>>(ei);

    // s1: independent prep
    eproj_kernel<<<(EE * 32) / 256, 256, 0, s1>>>(eattr, epw, epb);
    node_proj12<<<(NN * HID) / 256, 256, 0, s1>>>(x, l0Wl, l0bl, l0Wr, l0br);
    wprep_kernel<<<32, 256, 0, s1>>>(l0We, 0);
    cudaEventRecord(ev1, s1);
    cudaStreamWaitEvent(0, ev1, 0);

    // layer 0
    gemm_edge_score_mma<<<EE / 128, 256, ESM_BYTES>>>(l0att);
    node_fused_kernel<false, false><<<NN / 4, 128>>>(l0bias, lng, lnb, nullptr);

    // layers 1..3 (residual)
    for (int i = 0; i < 3; i++) {
        wprep3_kernel<<<96, 256>>>(Wl + i * HID * HID, Wr + i * HID * HID,
                                   We + i * HID * HID);
        dim3 ng(NTILES, 2);
        gemm_node_mma<<<ng, 256, ESM_BYTES>>>(bl + i * HID, br + i * HID);
        gemm_edge_score_mma<<<EE / 128, 256, ESM_BYTES>>>(att + i * HID);
        if (i < 2)
            node_fused_kernel<true, false><<<NN / 4, 128>>>(
                bias + i * HID, lng + (i + 1) * HID, lnb + (i + 1) * HID, nullptr);
        else
            node_fused_kernel<true, true><<<NN / 4, 128>>>(
                bias + i * HID, lng + (i + 1) * HID, lnb + (i + 1) * HID, out);
    }
}

// round 16
// speedup vs baseline: 1.0064x; 1.0064x over previous
#include <cuda_runtime.h>
#include <cuda_bf16.h>
#include <math.h>
#include <stdint.h>

#define NN 100000
#define EE 800000
#define HID 128
#define NH 4
#define DH 32
#define NBLK ((NN + 1023) / 1024)   // 98
#define NPAD 100096
#define NTILES ((NN + 127) / 128)   // 782
#define EPAD 68
#define TW (128 * EPAD)             // words per 128-row image (8704)
#define TB (TW * 4)                 // bytes per image (34816)
#define ESM_BYTES (3 * TB)          // Whi | Ahi | Alo(->Wlo) = 104448 B (2 blocks/SM)
#define XLPAD 132                   // xl prefetch row stride (floats)

// ---------------- scratch (static device globals; no allocation) ----------------
__device__ unsigned int g_Ahi[(size_t)EE * 64];   // edge feats bf16-hi pairs (CSR order)
__device__ unsigned int g_Alo[(size_t)EE * 64];
__device__ unsigned int g_hhi[(size_t)NPAD * 64]; // hidden bf16 pair images
__device__ unsigned int g_hlo[(size_t)NPAD * 64];
__device__ float g_xl[NN * HID];
__device__ float g_xr[NN * HID];
__device__ float g_h [NN * HID];
__device__ float g_score[EE * NH];                // CSR-position-indexed
// 10 W images: [0]=l0 We; layer i (1..3): [1+3(i-1)]=Wl, [+1]=Wr, [+2]=We
__device__ unsigned int g_Wimg_hi[10 * 8192];
__device__ unsigned int g_Wimg_lo[10 * 8192];
__device__ int g_deg[NN], g_cursor[NN], g_rowptr[NN + 1];
__device__ int g_pos[EE];                         // edge id -> CSR position
__device__ int2 g_sd[EE];                         // (src, dst) per CSR position
__device__ int g_bsum[NBLK], g_boff[NBLK];

// ---------------- helpers ----------------
__device__ __forceinline__ float fast_silu(float z) {
    return __fdividef(z, 1.0f + __expf(-z));
}
__device__ __forceinline__ unsigned int packbf2(float x, float y) {
    __nv_bfloat162 t = __floats2bfloat162_rn(x, y);
    return *(unsigned int*)&t;
}
__device__ __forceinline__ void bf_split(float x, float& hi, float& lo) {
    __nv_bfloat16 h = __float2bfloat16_rn(x);
    hi = __bfloat162float(h);
    lo = x - hi;
}
__device__ __forceinline__ void mma_bf16(float c[4],
                                         unsigned int a0, unsigned int a1,
                                         unsigned int a2, unsigned int a3,
                                         unsigned int b0, unsigned int b1) {
    asm volatile("mma.sync.aligned.m16n8k16.row.col.f32.bf16.bf16.f32 "
                 "{%0,%1,%2,%3}, {%4,%5,%6,%7}, {%8,%9}, {%0,%1,%2,%3};"
                 : "+f"(c[0]), "+f"(c[1]), "+f"(c[2]), "+f"(c[3])
                 : "r"(a0), "r"(a1), "r"(a2), "r"(a3), "r"(b0), "r"(b1));
}
__device__ __forceinline__ void ldsm4(unsigned int r[4], uint32_t addr) {
    asm volatile("ldmatrix.sync.aligned.m8n8.x4.shared.b16 {%0,%1,%2,%3}, [%4];"
                 : "=r"(r[0]), "=r"(r[1]), "=r"(r[2]), "=r"(r[3]) : "r"(addr));
}
__device__ __forceinline__ uint32_t smem_u32(const void* p) {
    uint32_t a;
    asm("{ .reg .u64 t; cvta.to.shared.u64 t, %1; cvt.u32.u64 %0, t; }" : "=r"(a) : "l"(p));
    return a;
}
__device__ __forceinline__ void cp16(uint32_t d, const void* s) {
    size_t gs = __cvta_generic_to_global((void*)s);
    asm volatile("cp.async.cg.shared.global [%0], [%1], 16;"
                 :: "r"(d), "l"((unsigned long long)gs) : "memory");
}
__device__ __forceinline__ void cp_commit() {
    asm volatile("cp.async.commit_group;" ::: "memory");
}
template <int N>
__device__ __forceinline__ void cp_wait() {
    asm volatile("cp.async.wait_group %0;" :: "n"(N) : "memory");
}

// ---------------- CSR build (by dst) ----------------
__global__ void zero_kernel() {
    int i = blockIdx.x * blockDim.x + threadIdx.x;
    if (i < NN) { g_deg[i] = 0; g_cursor[i] = 0; }
    if (i < (NPAD - NN) * 64) {
        g_hhi[(size_t)NN * 64 + i] = 0;
        g_hlo[(size_t)NN * 64 + i] = 0;
    }
}
__global__ void hist_kernel(const int* __restrict__ ei) {
    int e = blockIdx.x * blockDim.x + threadIdx.x;
    if (e < EE) atomicAdd(&g_deg[ei[EE + e]], 1);
}
__global__ void deg_block_sum() {
    __shared__ int sh[1024];
    int i = blockIdx.x * 1024 + threadIdx.x;
    sh[threadIdx.x] = (i < NN) ? g_deg[i] : 0;
    __syncthreads();
    for (int off = 512; off; off >>= 1) {
        if (threadIdx.x < off) sh[threadIdx.x] += sh[threadIdx.x + off];
        __syncthreads();
    }
    if (threadIdx.x == 0) g_bsum[blockIdx.x] = sh[0];
}
__global__ void bsum_scan() {
    __shared__ int sh[128];
    int t = threadIdx.x;
    int v = (t < NBLK) ? g_bsum[t] : 0;
    sh[t] = v;
    __syncthreads();
    for (int off = 1; off < 128; off <<= 1) {
        int u = (t >= off) ? sh[t - off] : 0;
        __syncthreads();
        sh[t] += u;
        __syncthreads();
    }
    if (t < NBLK) g_boff[t] = sh[t] - v;
}
__global__ void rowptr_kernel() {
    __shared__ int sh[1024];
    int i = blockIdx.x * 1024 + threadIdx.x;
    int v = (i < NN) ? g_deg[i] : 0;
    sh[threadIdx.x] = v;
    __syncthreads();
    for (int off = 1; off < 1024; off <<= 1) {
        int u = (threadIdx.x >= off) ? sh[threadIdx.x - off] : 0;
        __syncthreads();
        sh[threadIdx.x] += u;
        __syncthreads();
    }
    if (i < NN) g_rowptr[i + 1] = sh[threadIdx.x] + g_boff[blockIdx.x];
    if (i == 0) g_rowptr[0] = 0;
}
__global__ void scatter_kernel(const int* __restrict__ ei) {
    int e = blockIdx.x * blockDim.x + threadIdx.x;
    if (e < EE) {
        int src = ei[e];
        int d = ei[EE + e];
        int pos = g_rowptr[d] + atomicAdd(&g_cursor[d], 1);
        g_pos[e] = pos;
        g_sd[pos] = make_int2(src, d);
    }
}

// -------- edge feature projection: bf16 hi/lo images at CSR positions ----------
__global__ void eproj_kernel(const float* __restrict__ attr,
                             const float* __restrict__ W,
                             const float* __restrict__ b) {
    int idx = blockIdx.x * blockDim.x + threadIdx.x;   // E*32 threads
    int e = idx >> 5, c4 = (idx & 31) << 2;
    float a0 = __ldg(&attr[e * 3 + 0]);
    float a1 = __ldg(&attr[e * 3 + 1]);
    float a2 = __ldg(&attr[e * 3 + 2]);
    float v[4];
#pragma unroll
    for (int u = 0; u < 4; u++) {
        int j = c4 + u;
        float z = __ldg(&b[j]);
        z = fmaf(a0, __ldg(&W[j]),           z);
        z = fmaf(a1, __ldg(&W[HID + j]),     z);
        z = fmaf(a2, __ldg(&W[2 * HID + j]), z);
        v[u] = fast_silu(z);
    }
    float h0, l0, h1, l1, h2, l2, h3, l3;
    bf_split(v[0], h0, l0); bf_split(v[1], h1, l1);
    bf_split(v[2], h2, l2); bf_split(v[3], h3, l3);
    int pos = __ldg(&g_pos[e]);
    size_t base = (size_t)pos * 64 + (c4 >> 1);
    *(uint2*)&g_Ahi[base] = make_uint2(packbf2(h0, h1), packbf2(h2, h3));
    *(uint2*)&g_Alo[base] = make_uint2(packbf2(l0, l1), packbf2(l2, l3));
}

// ------ all 10 W images in one launch (l0We + 3x{Wl,Wr,We}) ------
__global__ void wprep_all(const float* __restrict__ l0We,
                          const float* __restrict__ Wl,
                          const float* __restrict__ Wr,
                          const float* __restrict__ We) {
    int idx = blockIdx.x * 256 + threadIdx.x;   // 10*8192 = 81920
    int img = idx >> 13, id = idx & 8191;
    const float* W;
    if (img == 0) {
        W = l0We;
    } else {
        int L = (img - 1) / 3, m = (img - 1) % 3;
        W = ((m == 0) ? Wl : (m == 1) ? Wr : We) + L * HID * HID;
    }
    int n = id >> 6, kw = id & 63;
    float w0 = __ldg(&W[(2 * kw) * HID + n]);
    float w1 = __ldg(&W[(2 * kw + 1) * HID + n]);
    float h0, l0, h1, l1;
    bf_split(w0, h0, l0);
    bf_split(w1, h1, l1);
    g_Wimg_hi[img * 8192 + id] = packbf2(h0, h1);
    g_Wimg_lo[img * 8192 + id] = packbf2(l0, l1);
}

// ---- one bf16 mma pass over the tile via ldmatrix (8 K-steps) ----
__device__ __forceinline__ void pass_mma(float acc[2][8][4],
                                         uint32_t aBase, uint32_t bBase,
                                         int mb, int nb, int lane) {
    uint32_t aoff = (uint32_t)(((mb + (lane & 15)) * EPAD + ((lane >> 4) << 2)) * 4);
    uint32_t boff = (uint32_t)(((nb + (lane & 7) + ((lane >> 4) << 3)) * EPAD
                                + (((lane >> 3) & 1) << 2)) * 4);
    uint32_t a0a = aBase + aoff;
    uint32_t a1a = a0a + 16 * EPAD * 4;
    uint32_t bja = bBase + boff;
#pragma unroll
    for (int ks = 0; ks < 8; ks++) {
        unsigned int a0[4], a1[4];
        ldsm4(a0, a0a + ks * 32);
        ldsm4(a1, a1a + ks * 32);
        unsigned int b[4][4];
#pragma unroll
        for (int jj = 0; jj < 4; jj++)
            ldsm4(b[jj], bja + (uint32_t)(jj * 16 * EPAD * 4) + ks * 32);
#pragma unroll
        for (int jj = 0; jj < 4; jj++) {
            mma_bf16(acc[0][2 * jj + 0], a0[0], a0[1], a0[2], a0[3], b[jj][0], b[jj][1]);
            mma_bf16(acc[0][2 * jj + 1], a0[0], a0[1], a0[2], a0[3], b[jj][2], b[jj][3]);
            mma_bf16(acc[1][2 * jj + 0], a1[0], a1[1], a1[2], a1[3], b[jj][0], b[jj][1]);
            mma_bf16(acc[1][2 * jj + 1], a1[0], a1[1], a1[2], a1[3], b[jj][2], b[jj][3]);
        }
    }
}

// ---- staging: Whi + sequential A (hi/lo), one cp.async group ----
__device__ __forceinline__ void stage_all(uint32_t sb, const unsigned int* ghi,
                                          const unsigned int* glo,
                                          const unsigned int* gWhi,
                                          int m0, int tid) {
#pragma unroll
    for (int i = 0; i < 8; i++) {
        int idx = i * 256 + tid;
        int row = idx >> 4, c = (idx & 15) << 2;
        uint32_t doff = (uint32_t)(row * EPAD + c) * 4;
        cp16(sb + TB + doff, &ghi[(size_t)(m0 + row) * 64 + c]);
        cp16(sb + 2 * TB + doff, &glo[(size_t)(m0 + row) * 64 + c]);
        cp16(sb + doff, &gWhi[(size_t)row * 64 + c]);
    }
    cp_commit();
}
__device__ __forceinline__ void stage_Wlo(uint32_t dst, const unsigned int* gWlo,
                                          int tid) {
#pragma unroll
    for (int i = 0; i < 8; i++) {
        int idx = i * 256 + tid;
        int row = idx >> 4, c = (idx & 15) << 2;
        cp16(dst + (uint32_t)(row * EPAD + c) * 4, &gWlo[(size_t)row * 64 + c]);
    }
    cp_commit();
}
__device__ __forceinline__ void prefetch_xl(uint32_t dstbase, int p0, int tid) {
#pragma unroll
    for (int i = 0; i < 8; i++) {
        int idx = i * 256 + tid;
        int row = idx >> 5;
        int c = (idx & 31) << 2;
        int src = __ldg(&g_sd[p0 + row].x);
        cp16(dstbase + (uint32_t)(row * XLPAD + c) * 4,
             &g_xl[(size_t)src * HID + c]);
    }
    cp_commit();
}

// ========= edge GEMM + fused score (3-image smem, 2 blocks/SM) =========
__global__ __launch_bounds__(256, 2) void gemm_edge_score_mma(
        const float* __restrict__ att,
        const unsigned int* __restrict__ gWhi,
        const unsigned int* __restrict__ gWlo) {
    extern __shared__ __align__(16) unsigned int esm[];
    uint32_t sb = smem_u32(esm);
    int tid = threadIdx.x;
    int m0 = blockIdx.x * 128;

    stage_all(sb, g_Ahi, g_Alo, gWhi, m0, tid);
    cp_wait<0>();
    __syncthreads();

    int wid = tid >> 5, lane = tid & 31, g = lane >> 2, q = lane & 3;
    int mb = (wid & 3) * 32;
    int nb = (wid >> 2) * 64;

    float acc[2][8][4];
#pragma unroll
    for (int t = 0; t < 2; t++)
#pragma unroll
        for (int j = 0; j < 8; j++)
#pragma unroll
            for (int c = 0; c < 4; c++) acc[t][j][c] = 0.f;

    // p0: (Alo, Whi) — Alo dead afterwards
    pass_mma(acc, sb + 2 * TB, sb, mb, nb, lane);
    __syncthreads();
    stage_Wlo(sb + 2 * TB, gWlo, tid);              // Wlo -> Alo space

    // p1: (Ahi, Whi) — Whi dead afterwards (Wlo load overlaps)
    pass_mma(acc, sb + TB, sb, mb, nb, lane);
    __syncthreads();
    prefetch_xl(sb, m0, tid);                        // xl rows 0..63 -> Whi space
    cp_wait<1>();                                    // Wlo done
    __syncthreads();

    // p2: (Ahi, Wlo) (xl load overlaps)
    pass_mma(acc, sb + TB, sb + 2 * TB, mb, nb, lane);
    cp_wait<0>();
    __syncthreads();

    const float* xlb0 = (const float*)esm;
    float2 attv[8];
#pragma unroll
    for (int j = 0; j < 8; j++)
        attv[j] = *(const float2*)&att[nb + 8 * j + 2 * q];

#pragma unroll
    for (int t = 0; t < 2; t++) {
#pragma unroll
        for (int rr = 0; rr < 2; rr++) {
            int row = mb + 16 * t + 8 * rr + g;
            int pos = m0 + row;
            int2 sd = __ldg(&g_sd[pos]);
            const float* xlp = (row < 64) ? (xlb0 + row * XLPAD)
                                          : &g_xl[(size_t)sd.x * HID];
            const float* xrp = &g_xr[(size_t)sd.y * HID];
            float p0 = 0.f, p1 = 0.f;
#pragma unroll
            for (int j = 0; j < 8; j++) {
                int cc = nb + 8 * j + 2 * q;
                float2 xl = *(const float2*)&xlp[cc];
                float2 xr = *(const float2*)&xrp[cc];
                float e0 = acc[t][j][rr * 2 + 0] + xl.x + xr.x;
                float e1 = acc[t][j][rr * 2 + 1] + xl.y + xr.y;
                e0 = (e0 > 0.f) ? e0 : 0.2f * e0;
                e1 = (e1 > 0.f) ? e1 : 0.2f * e1;
                float ps = fmaf(e0, attv[j].x, e1 * attv[j].y);
                if (j < 4) p0 += ps; else p1 += ps;
            }
            p0 += __shfl_xor_sync(0xffffffffu, p0, 1);
            p0 += __shfl_xor_sync(0xffffffffu, p0, 2);
            p1 += __shfl_xor_sync(0xffffffffu, p1, 1);
            p1 += __shfl_xor_sync(0xffffffffu, p1, 2);
            if (q == 0)
                *(float2*)&g_score[(size_t)pos * 4 + (nb >> 5)] =
                    make_float2(p0, p1);
        }
    }
}

// ============ node GEMM (3-image smem, 2 blocks/SM) ==========
__global__ __launch_bounds__(256, 2) void gemm_node_mma(
        const float* __restrict__ bl, const float* __restrict__ br,
        const unsigned int* __restrict__ whiL, const unsigned int* __restrict__ wloL,
        const unsigned int* __restrict__ whiR, const unsigned int* __restrict__ wloR) {
    extern __shared__ __align__(16) unsigned int esm[];
    uint32_t sb = smem_u32(esm);
    int tid = threadIdx.x;
    int m0 = blockIdx.x * 128;

    const unsigned int* gWhi = blockIdx.y ? whiR : whiL;
    const unsigned int* gWlo = blockIdx.y ? wloR : wloL;
    const float* bias = blockIdx.y ? br : bl;
    float* C = blockIdx.y ? g_xr : g_xl;

    stage_all(sb, g_hhi, g_hlo, gWhi, m0, tid);
    cp_wait<0>();
    __syncthreads();

    int wid = tid >> 5, lane = tid & 31, g = lane >> 2, q = lane & 3;
    int mb = (wid & 3) * 32;
    int nb = (wid >> 2) * 64;

    float acc[2][8][4];
#pragma unroll
    for (int t = 0; t < 2; t++)
#pragma unroll
        for (int j = 0; j < 8; j++)
#pragma unroll
            for (int c = 0; c < 4; c++) acc[t][j][c] = 0.f;

    pass_mma(acc, sb + 2 * TB, sb, mb, nb, lane);   // (Alo, Whi)
    __syncthreads();
    stage_Wlo(sb + 2 * TB, gWlo, tid);              // Wlo -> Alo space
    pass_mma(acc, sb + TB, sb, mb, nb, lane);       // (Ahi, Whi)
    cp_wait<0>();
    __syncthreads();
    pass_mma(acc, sb + TB, sb + 2 * TB, mb, nb, lane); // (Ahi, Wlo)

    float2 biasv[8];
#pragma unroll
    for (int j = 0; j < 8; j++)
        biasv[j] = *(const float2*)&bias[nb + 8 * j + 2 * q];

#pragma unroll
    for (int t = 0; t < 2; t++) {
#pragma unroll
        for (int rr = 0; rr < 2; rr++) {
            int m = m0 + mb + 16 * t + 8 * rr + g;
            if (m < NN) {
#pragma unroll
                for (int j = 0; j < 8; j++) {
                    int cc = nb + 8 * j + 2 * q;
                    *(float2*)&C[(size_t)m * HID + cc] =
                        make_float2(acc[t][j][rr * 2 + 0] + biasv[j].x,
                                    acc[t][j][rr * 2 + 1] + biasv[j].y);
                }
            }
        }
    }
}

// ---------------- layer-0 node projection (K=12) ----------------
__global__ void node_proj12(const float* __restrict__ x,
                            const float* __restrict__ Wl, const float* __restrict__ bl,
                            const float* __restrict__ Wr, const float* __restrict__ br) {
    int idx = blockIdx.x * blockDim.x + threadIdx.x;
    int n = idx >> 7, j = idx & 127;
    float a = __ldg(&bl[j]);
    float b = __ldg(&br[j]);
#pragma unroll
    for (int k = 0; k < 12; k++) {
        float xv = __ldg(&x[n * 12 + k]);
        a = fmaf(xv, __ldg(&Wl[k * HID + j]), a);
        b = fmaf(xv, __ldg(&Wr[k * HID + j]), b);
    }
    g_xl[idx] = a;
    g_xr[idx] = b;
}

// ------- fused per-node: softmax + aggregate + bias + LN + SiLU (+res) ----------
template <bool RES, bool LAST>
__global__ void node_fused_kernel(const float* __restrict__ gat_bias,
                                  const float* __restrict__ lng,
                                  const float* __restrict__ lnb,
                                  float* __restrict__ dout) {
    int n = blockIdx.x * 4 + (threadIdx.x >> 5);
    int lane = threadIdx.x & 31;
    if (n >= NN) return;
    int s0 = g_rowptr[n];
    int s1 = g_rowptr[n + 1];

    float mx = -3.4e38f;
    for (int p = s0 * 4 + lane; p < s1 * 4; p += 32)
        mx = fmaxf(mx, g_score[p]);
    mx = fmaxf(mx, __shfl_xor_sync(0xffffffffu, mx, 4));
    mx = fmaxf(mx, __shfl_xor_sync(0xffffffffu, mx, 8));
    mx = fmaxf(mx, __shfl_xor_sync(0xffffffffu, mx, 16));

    float den = 0.f;
    for (int p = s0 * 4 + lane; p < s1 * 4; p += 32)
        den += __expf(g_score[p] - mx);
    den += __shfl_xor_sync(0xffffffffu, den, 4);
    den += __shfl_xor_sync(0xffffffffu, den, 8);
    den += __shfl_xor_sync(0xffffffffu, den, 16);
    float inv = __fdividef(1.f, den + 1e-16f);

    float acc0 = 0.f, acc1 = 0.f, acc2 = 0.f, acc3 = 0.f;
    int i = s0;
    for (; i + 1 < s1; i += 2) {     // unroll x2: two xl gathers in flight
        int srcA = g_sd[i].x;
        int srcB = g_sd[i + 1].x;
        float a = 0.f, b = 0.f;
        if (lane < 4) {
            a = __expf(g_score[(size_t)i * 4 + lane] - mx) * inv;
            b = __expf(g_score[(size_t)(i + 1) * 4 + lane] - mx) * inv;
        }
        const float* xlA = &g_xl[(size_t)srcA * HID];
        const float* xlB = &g_xl[(size_t)srcB * HID];
        float A0 = xlA[0 * DH + lane], A1 = xlA[1 * DH + lane];
        float A2 = xlA[2 * DH + lane], A3 = xlA[3 * DH + lane];
        float B0 = xlB[0 * DH + lane], B1 = xlB[1 * DH + lane];
        float B2 = xlB[2 * DH + lane], B3 = xlB[3 * DH + lane];
        acc0 = fmaf(A0, __shfl_sync(0xffffffffu, a, 0), acc0);
        acc1 = fmaf(A1, __shfl_sync(0xffffffffu, a, 1), acc1);
        acc2 = fmaf(A2, __shfl_sync(0xffffffffu, a, 2), acc2);
        acc3 = fmaf(A3, __shfl_sync(0xffffffffu, a, 3), acc3);
        acc0 = fmaf(B0, __shfl_sync(0xffffffffu, b, 0), acc0);
        acc1 = fmaf(B1, __shfl_sync(0xffffffffu, b, 1), acc1);
        acc2 = fmaf(B2, __shfl_sync(0xffffffffu, b, 2), acc2);
        acc3 = fmaf(B3, __shfl_sync(0xffffffffu, b, 3), acc3);
    }
    if (i < s1) {
        int src = g_sd[i].x;
        float a = 0.f;
        if (lane < 4) a = __expf(g_score[(size_t)i * 4 + lane] - mx) * inv;
        const float* xl = &g_xl[(size_t)src * HID];
        acc0 = fmaf(xl[0 * DH + lane], __shfl_sync(0xffffffffu, a, 0), acc0);
        acc1 = fmaf(xl[1 * DH + lane], __shfl_sync(0xffffffffu, a, 1), acc1);
        acc2 = fmaf(xl[2 * DH + lane], __shfl_sync(0xffffffffu, a, 2), acc2);
        acc3 = fmaf(xl[3 * DH + lane], __shfl_sync(0xffffffffu, a, 3), acc3);
    }

    float v0 = acc0 + __ldg(&gat_bias[0 * DH + lane]);
    float v1 = acc1 + __ldg(&gat_bias[1 * DH + lane]);
    float v2 = acc2 + __ldg(&gat_bias[2 * DH + lane]);
    float v3 = acc3 + __ldg(&gat_bias[3 * DH + lane]);

    float sm = v0 + v1 + v2 + v3;
#pragma unroll
    for (int off = 16; off; off >>= 1) sm += __shfl_xor_sync(0xffffffffu, sm, off);
    float mean = sm * (1.f / 128.f);
    float d0 = v0 - mean, d1 = v1 - mean, d2 = v2 - mean, d3 = v3 - mean;
    float sq = d0 * d0 + d1 * d1 + d2 * d2 + d3 * d3;
#pragma unroll
    for (int off = 16; off; off >>= 1) sq += __shfl_xor_sync(0xffffffffu, sq, off);
    float rstd = rsqrtf(sq * (1.f / 128.f) + 1e-5f);

#pragma unroll
    for (int h = 0; h < 4; h++) {
        int j = h * DH + lane;
        float d = (h == 0 ? d0 : h == 1 ? d1 : h == 2 ? d2 : d3);
        float t = fmaf(d * rstd, __ldg(&lng[j]), __ldg(&lnb[j]));
        float sil = fast_silu(t);
        float o = RES ? (g_h[n * HID + j] + sil) : sil;
        if (LAST) {
            dout[n * HID + j] = o;
        } else {
            g_h[n * HID + j] = o;
            float on = __shfl_down_sync(0xffffffffu, o, 1);
            if (!(lane & 1)) {
                float h0, l0, h1, l1;
                bf_split(o, h0, l0);
                bf_split(on, h1, l1);
                g_hhi[(size_t)n * 64 + (j >> 1)] = packbf2(h0, h1);
                g_hlo[(size_t)n * 64 + (j >> 1)] = packbf2(l0, l1);
            }
        }
    }
}

// ---------------- launch ----------------
extern "C" void kernel_launch(void* const* d_in, const int* in_sizes, int n_in,
                              void* d_out, int out_size) {
    const float* x     = (const float*)d_in[0];
    const int*   ei    = (const int*)  d_in[1];
    const float* eattr = (const float*)d_in[2];
    const float* epw   = (const float*)d_in[3];
    const float* epb   = (const float*)d_in[4];
    const float* l0Wl  = (const float*)d_in[5];
    const float* l0bl  = (const float*)d_in[6];
    const float* l0Wr  = (const float*)d_in[7];
    const float* l0br  = (const float*)d_in[8];
    const float* l0We  = (const float*)d_in[9];
    const float* l0att = (const float*)d_in[10];
    const float* l0bias= (const float*)d_in[11];
    const float* Wl    = (const float*)d_in[12];
    const float* bl    = (const float*)d_in[13];
    const float* Wr    = (const float*)d_in[14];
    const float* br    = (const float*)d_in[15];
    const float* We    = (const float*)d_in[16];
    const float* att   = (const float*)d_in[17];
    const float* bias  = (const float*)d_in[18];
    const float* lng   = (const float*)d_in[19];
    const float* lnb   = (const float*)d_in[20];
    float* out = (float*)d_out;

    static bool attr_set = false;
    if (!attr_set) {
        cudaFuncSetAttribute(gemm_edge_score_mma,
                             cudaFuncAttributeMaxDynamicSharedMemorySize, ESM_BYTES);
        cudaFuncSetAttribute(gemm_node_mma,
                             cudaFuncAttributeMaxDynamicSharedMemorySize, ESM_BYTES);
        attr_set = true;
    }

    // device pointers to image buffers
    unsigned int *dWhi, *dWlo;
    cudaGetSymbolAddress((void**)&dWhi, g_Wimg_hi);
    cudaGetSymbolAddress((void**)&dWlo, g_Wimg_lo);

    // CSR build (eproj needs g_pos)
    zero_kernel<<<(NN + 255) / 256, 256>>>();
    hist_kernel<<<(EE + 255) / 256, 256>>>(ei);
    deg_block_sum<<<NBLK, 1024>>>();
    bsum_scan<<<1, 128>>>();
    rowptr_kernel<<<NBLK, 1024>>>();
    scatter_kernel<<<(EE + 255) / 256, 256>>>(ei);

    // independent prep (all W images at once)
    eproj_kernel<<<(EE * 32) / 256, 256>>>(eattr, epw, epb);
    node_proj12<<<(NN * HID) / 256, 256>>>(x, l0Wl, l0bl, l0Wr, l0br);
    wprep_all<<<320, 256>>>(l0We, Wl, Wr, We);

    // layer 0
    gemm_edge_score_mma<<<EE / 128, 256, ESM_BYTES>>>(l0att, dWhi, dWlo);
    node_fused_kernel<false, false><<<NN / 4, 128>>>(l0bias, lng, lnb, nullptr);

    // layers 1..3 (residual)
    for (int i = 0; i < 3; i++) {
        int base = 1 + 3 * i;
        dim3 ng(NTILES, 2);
        gemm_node_mma<<<ng, 256, ESM_BYTES>>>(
            bl + i * HID, br + i * HID,
            dWhi + (size_t)(base + 0) * 8192, dWlo + (size_t)(base + 0) * 8192,
            dWhi + (size_t)(base + 1) * 8192, dWlo + (size_t)(base + 1) * 8192);
        gemm_edge_score_mma<<<EE / 128, 256, ESM_BYTES>>>(
            att + i * HID,
            dWhi + (size_t)(base + 2) * 8192, dWlo + (size_t)(base + 2) * 8192);
        if (i < 2)
            node_fused_kernel<true, false><<<NN / 4, 128>>>(
                bias + i * HID, lng + (i + 1) * HID, lnb + (i + 1) * HID, nullptr);
        else
            node_fused_kernel<true, true><<<NN / 4, 128>>>(
                bias + i * HID, lng + (i + 1) * HID, lnb + (i + 1) * HID, out);
    }
}

// round 17
// speedup vs baseline: 1.0199x; 1.0134x over previous
#include <cuda_runtime.h>
#include <cuda_bf16.h>
#include <math.h>
#include <stdint.h>

#define NN 100000
#define EE 800000
#define HID 128
#define NH 4
#define DH 32
#define NBLK ((NN + 1023) / 1024)   // 98
#define NPAD 100096
#define NTILES ((NN + 127) / 128)   // 782
#define EPAD 68
#define TW (128 * EPAD)             // words per 128-row image (8704)
#define TB (TW * 4)                 // bytes per image (34816)
#define ESM_BYTES (3 * TB)          // Whi | Ahi | Alo(->Wlo) = 104448 B (2 blocks/SM)
#define XLPAD 132                   // xl prefetch row stride (floats)

// ---------------- scratch (static device globals; no allocation) ----------------
__device__ unsigned int g_Ahi[(size_t)EE * 64];   // edge feats bf16-hi pairs (CSR order)
__device__ unsigned int g_Alo[(size_t)EE * 64];
__device__ unsigned int g_hhi[(size_t)NPAD * 64]; // hidden bf16 pair images
__device__ unsigned int g_hlo[(size_t)NPAD * 64];
__device__ float g_xl[NN * HID];
__device__ float g_xr[NN * HID];
__device__ float g_h [NN * HID];
__device__ float g_score[EE * NH];                // CSR-position-indexed
// 10 W images: [0]=l0 We; layer i (1..3): [1+3(i-1)]=Wl, [+1]=Wr, [+2]=We
__device__ unsigned int g_Wimg_hi[10 * 8192];
__device__ unsigned int g_Wimg_lo[10 * 8192];
__device__ int g_deg[NN], g_cursor[NN], g_rowptr[NN + 1];
__device__ int g_pos[EE];                         // edge id -> CSR position
__device__ int2 g_sd[EE];                         // (src, dst) per CSR position
__device__ int g_bsum[NBLK], g_boff[NBLK];

// ---------------- helpers ----------------
__device__ __forceinline__ float fast_silu(float z) {
    return __fdividef(z, 1.0f + __expf(-z));
}
__device__ __forceinline__ unsigned int packbf2(float x, float y) {
    __nv_bfloat162 t = __floats2bfloat162_rn(x, y);
    return *(unsigned int*)&t;
}
__device__ __forceinline__ void bf_split(float x, float& hi, float& lo) {
    __nv_bfloat16 h = __float2bfloat16_rn(x);
    hi = __bfloat162float(h);
    lo = x - hi;
}
__device__ __forceinline__ void mma_bf16(float c[4],
                                         unsigned int a0, unsigned int a1,
                                         unsigned int a2, unsigned int a3,
                                         unsigned int b0, unsigned int b1) {
    asm volatile("mma.sync.aligned.m16n8k16.row.col.f32.bf16.bf16.f32 "
                 "{%0,%1,%2,%3}, {%4,%5,%6,%7}, {%8,%9}, {%0,%1,%2,%3};"
                 : "+f"(c[0]), "+f"(c[1]), "+f"(c[2]), "+f"(c[3])
                 : "r"(a0), "r"(a1), "r"(a2), "r"(a3), "r"(b0), "r"(b1));
}
__device__ __forceinline__ void ldsm4(unsigned int r[4], uint32_t addr) {
    asm volatile("ldmatrix.sync.aligned.m8n8.x4.shared.b16 {%0,%1,%2,%3}, [%4];"
                 : "=r"(r[0]), "=r"(r[1]), "=r"(r[2]), "=r"(r[3]) : "r"(addr));
}
__device__ __forceinline__ uint32_t smem_u32(const void* p) {
    uint32_t a;
    asm("{ .reg .u64 t; cvta.to.shared.u64 t, %1; cvt.u32.u64 %0, t; }" : "=r"(a) : "l"(p));
    return a;
}
__device__ __forceinline__ void cp16(uint32_t d, const void* s) {
    size_t gs = __cvta_generic_to_global((void*)s);
    asm volatile("cp.async.cg.shared.global [%0], [%1], 16;"
                 :: "r"(d), "l"((unsigned long long)gs) : "memory");
}
__device__ __forceinline__ void cp_commit() {
    asm volatile("cp.async.commit_group;" ::: "memory");
}
template <int N>
__device__ __forceinline__ void cp_wait() {
    asm volatile("cp.async.wait_group %0;" :: "n"(N) : "memory");
}

// ---------------- CSR build (by dst) ----------------
__global__ void zero_kernel() {
    int i = blockIdx.x * blockDim.x + threadIdx.x;
    if (i < NN) { g_deg[i] = 0; g_cursor[i] = 0; }
    if (i < (NPAD - NN) * 64) {
        g_hhi[(size_t)NN * 64 + i] = 0;
        g_hlo[(size_t)NN * 64 + i] = 0;
    }
}
__global__ void hist_kernel(const int* __restrict__ ei) {
    int e = blockIdx.x * blockDim.x + threadIdx.x;
    if (e < EE) atomicAdd(&g_deg[ei[EE + e]], 1);
}
__global__ void deg_block_sum() {
    __shared__ int sh[1024];
    int i = blockIdx.x * 1024 + threadIdx.x;
    sh[threadIdx.x] = (i < NN) ? g_deg[i] : 0;
    __syncthreads();
    for (int off = 512; off; off >>= 1) {
        if (threadIdx.x < off) sh[threadIdx.x] += sh[threadIdx.x + off];
        __syncthreads();
    }
    if (threadIdx.x == 0) g_bsum[blockIdx.x] = sh[0];
}
__global__ void bsum_scan() {
    __shared__ int sh[128];
    int t = threadIdx.x;
    int v = (t < NBLK) ? g_bsum[t] : 0;
    sh[t] = v;
    __syncthreads();
    for (int off = 1; off < 128; off <<= 1) {
        int u = (t >= off) ? sh[t - off] : 0;
        __syncthreads();
        sh[t] += u;
        __syncthreads();
    }
    if (t < NBLK) g_boff[t] = sh[t] - v;
}
__global__ void rowptr_kernel() {
    __shared__ int sh[1024];
    int i = blockIdx.x * 1024 + threadIdx.x;
    int v = (i < NN) ? g_deg[i] : 0;
    sh[threadIdx.x] = v;
    __syncthreads();
    for (int off = 1; off < 1024; off <<= 1) {
        int u = (threadIdx.x >= off) ? sh[threadIdx.x - off] : 0;
        __syncthreads();
        sh[threadIdx.x] += u;
        __syncthreads();
    }
    if (i < NN) g_rowptr[i + 1] = sh[threadIdx.x] + g_boff[blockIdx.x];
    if (i == 0) g_rowptr[0] = 0;
}
__global__ void scatter_kernel(const int* __restrict__ ei) {
    int e = blockIdx.x * blockDim.x + threadIdx.x;
    if (e < EE) {
        int src = ei[e];
        int d = ei[EE + e];
        int pos = g_rowptr[d] + atomicAdd(&g_cursor[d], 1);
        g_pos[e] = pos;
        g_sd[pos] = make_int2(src, d);
    }
}

// -------- edge feature projection: bf16 hi/lo images at CSR positions ----------
__global__ void eproj_kernel(const float* __restrict__ attr,
                             const float* __restrict__ W,
                             const float* __restrict__ b) {
    int idx = blockIdx.x * blockDim.x + threadIdx.x;   // E*32 threads
    int e = idx >> 5, c4 = (idx & 31) << 2;
    float a0 = __ldg(&attr[e * 3 + 0]);
    float a1 = __ldg(&attr[e * 3 + 1]);
    float a2 = __ldg(&attr[e * 3 + 2]);
    float v[4];
#pragma unroll
    for (int u = 0; u < 4; u++) {
        int j = c4 + u;
        float z = __ldg(&b[j]);
        z = fmaf(a0, __ldg(&W[j]),           z);
        z = fmaf(a1, __ldg(&W[HID + j]),     z);
        z = fmaf(a2, __ldg(&W[2 * HID + j]), z);
        v[u] = fast_silu(z);
    }
    float h0, l0, h1, l1, h2, l2, h3, l3;
    bf_split(v[0], h0, l0); bf_split(v[1], h1, l1);
    bf_split(v[2], h2, l2); bf_split(v[3], h3, l3);
    int pos = __ldg(&g_pos[e]);
    size_t base = (size_t)pos * 64 + (c4 >> 1);
    *(uint2*)&g_Ahi[base] = make_uint2(packbf2(h0, h1), packbf2(h2, h3));
    *(uint2*)&g_Alo[base] = make_uint2(packbf2(l0, l1), packbf2(l2, l3));
}

// ------ all 10 W images in one launch (l0We + 3x{Wl,Wr,We}) ------
__global__ void wprep_all(const float* __restrict__ l0We,
                          const float* __restrict__ Wl,
                          const float* __restrict__ Wr,
                          const float* __restrict__ We) {
    int idx = blockIdx.x * 256 + threadIdx.x;   // 10*8192 = 81920
    int img = idx >> 13, id = idx & 8191;
    const float* W;
    if (img == 0) {
        W = l0We;
    } else {
        int L = (img - 1) / 3, m = (img - 1) % 3;
        W = ((m == 0) ? Wl : (m == 1) ? Wr : We) + L * HID * HID;
    }
    int n = id >> 6, kw = id & 63;
    float w0 = __ldg(&W[(2 * kw) * HID + n]);
    float w1 = __ldg(&W[(2 * kw + 1) * HID + n]);
    float h0, l0, h1, l1;
    bf_split(w0, h0, l0);
    bf_split(w1, h1, l1);
    g_Wimg_hi[img * 8192 + id] = packbf2(h0, h1);
    g_Wimg_lo[img * 8192 + id] = packbf2(l0, l1);
}

// ---- one bf16 mma pass over the tile via ldmatrix (8 K-steps) ----
__device__ __forceinline__ void pass_mma(float acc[2][8][4],
                                         uint32_t aBase, uint32_t bBase,
                                         int mb, int nb, int lane) {
    uint32_t aoff = (uint32_t)(((mb + (lane & 15)) * EPAD + ((lane >> 4) << 2)) * 4);
    uint32_t boff = (uint32_t)(((nb + (lane & 7) + ((lane >> 4) << 3)) * EPAD
                                + (((lane >> 3) & 1) << 2)) * 4);
    uint32_t a0a = aBase + aoff;
    uint32_t a1a = a0a + 16 * EPAD * 4;
    uint32_t bja = bBase + boff;
#pragma unroll
    for (int ks = 0; ks < 8; ks++) {
        unsigned int a0[4], a1[4];
        ldsm4(a0, a0a + ks * 32);
        ldsm4(a1, a1a + ks * 32);
        unsigned int b[4][4];
#pragma unroll
        for (int jj = 0; jj < 4; jj++)
            ldsm4(b[jj], bja + (uint32_t)(jj * 16 * EPAD * 4) + ks * 32);
#pragma unroll
        for (int jj = 0; jj < 4; jj++) {
            mma_bf16(acc[0][2 * jj + 0], a0[0], a0[1], a0[2], a0[3], b[jj][0], b[jj][1]);
            mma_bf16(acc[0][2 * jj + 1], a0[0], a0[1], a0[2], a0[3], b[jj][2], b[jj][3]);
            mma_bf16(acc[1][2 * jj + 0], a1[0], a1[1], a1[2], a1[3], b[jj][0], b[jj][1]);
            mma_bf16(acc[1][2 * jj + 1], a1[0], a1[1], a1[2], a1[3], b[jj][2], b[jj][3]);
        }
    }
}

// ---- staging: Whi + sequential A (hi/lo), one cp.async group ----
__device__ __forceinline__ void stage_all(uint32_t sb, const unsigned int* ghi,
                                          const unsigned int* glo,
                                          const unsigned int* gWhi,
                                          int m0, int tid) {
#pragma unroll
    for (int i = 0; i < 8; i++) {
        int idx = i * 256 + tid;
        int row = idx >> 4, c = (idx & 15) << 2;
        uint32_t doff = (uint32_t)(row * EPAD + c) * 4;
        cp16(sb + TB + doff, &ghi[(size_t)(m0 + row) * 64 + c]);
        cp16(sb + 2 * TB + doff, &glo[(size_t)(m0 + row) * 64 + c]);
        cp16(sb + doff, &gWhi[(size_t)row * 64 + c]);
    }
    cp_commit();
}
__device__ __forceinline__ void stage_Wlo(uint32_t dst, const unsigned int* gWlo,
                                          int tid) {
#pragma unroll
    for (int i = 0; i < 8; i++) {
        int idx = i * 256 + tid;
        int row = idx >> 4, c = (idx & 15) << 2;
        cp16(dst + (uint32_t)(row * EPAD + c) * 4, &gWlo[(size_t)row * 64 + c]);
    }
    cp_commit();
}
__device__ __forceinline__ void prefetch_xl(uint32_t dstbase, int p0, int tid) {
#pragma unroll
    for (int i = 0; i < 8; i++) {
        int idx = i * 256 + tid;
        int row = idx >> 5;
        int c = (idx & 31) << 2;
        int src = __ldg(&g_sd[p0 + row].x);
        cp16(dstbase + (uint32_t)(row * XLPAD + c) * 4,
             &g_xl[(size_t)src * HID + c]);
    }
    cp_commit();
}

// ========= edge GEMM + fused score (3-image smem, 2 blocks/SM) =========
__global__ __launch_bounds__(256, 2) void gemm_edge_score_mma(
        const float* __restrict__ att,
        const unsigned int* __restrict__ gWhi,
        const unsigned int* __restrict__ gWlo) {
    extern __shared__ __align__(16) unsigned int esm[];
    uint32_t sb = smem_u32(esm);
    int tid = threadIdx.x;
    int m0 = blockIdx.x * 128;

    stage_all(sb, g_Ahi, g_Alo, gWhi, m0, tid);
    cp_wait<0>();
    __syncthreads();

    int wid = tid >> 5, lane = tid & 31, g = lane >> 2, q = lane & 3;
    int mb = (wid & 3) * 32;
    int nb = (wid >> 2) * 64;

    float acc[2][8][4];
#pragma unroll
    for (int t = 0; t < 2; t++)
#pragma unroll
        for (int j = 0; j < 8; j++)
#pragma unroll
            for (int c = 0; c < 4; c++) acc[t][j][c] = 0.f;

    // p0: (Alo, Whi) — Alo dead afterwards
    pass_mma(acc, sb + 2 * TB, sb, mb, nb, lane);
    __syncthreads();
    stage_Wlo(sb + 2 * TB, gWlo, tid);              // Wlo -> Alo space

    // p1: (Ahi, Whi) — Whi dead afterwards (Wlo load overlaps)
    pass_mma(acc, sb + TB, sb, mb, nb, lane);
    __syncthreads();
    prefetch_xl(sb, m0, tid);                        // xl rows 0..63 -> Whi space
    cp_wait<1>();                                    // Wlo done
    __syncthreads();

    // p2: (Ahi, Wlo) (xl load overlaps)
    pass_mma(acc, sb + TB, sb + 2 * TB, mb, nb, lane);
    cp_wait<0>();
    __syncthreads();

    const float* xlb0 = (const float*)esm;
    float2 attv[8];
#pragma unroll
    for (int j = 0; j < 8; j++)
        attv[j] = *(const float2*)&att[nb + 8 * j + 2 * q];

#pragma unroll
    for (int t = 0; t < 2; t++) {
#pragma unroll
        for (int rr = 0; rr < 2; rr++) {
            int row = mb + 16 * t + 8 * rr + g;
            int pos = m0 + row;
            int2 sd = __ldg(&g_sd[pos]);
            const float* xlp = (row < 64) ? (xlb0 + row * XLPAD)
                                          : &g_xl[(size_t)sd.x * HID];
            const float* xrp = &g_xr[(size_t)sd.y * HID];
            float p0 = 0.f, p1 = 0.f;
#pragma unroll
            for (int j = 0; j < 8; j++) {
                int cc = nb + 8 * j + 2 * q;
                float2 xl = *(const float2*)&xlp[cc];
                float2 xr = *(const float2*)&xrp[cc];
                float e0 = acc[t][j][rr * 2 + 0] + xl.x + xr.x;
                float e1 = acc[t][j][rr * 2 + 1] + xl.y + xr.y;
                e0 = (e0 > 0.f) ? e0 : 0.2f * e0;
                e1 = (e1 > 0.f) ? e1 : 0.2f * e1;
                float ps = fmaf(e0, attv[j].x, e1 * attv[j].y);
                if (j < 4) p0 += ps; else p1 += ps;
            }
            p0 += __shfl_xor_sync(0xffffffffu, p0, 1);
            p0 += __shfl_xor_sync(0xffffffffu, p0, 2);
            p1 += __shfl_xor_sync(0xffffffffu, p1, 1);
            p1 += __shfl_xor_sync(0xffffffffu, p1, 2);
            if (q == 0)
                *(float2*)&g_score[(size_t)pos * 4 + (nb >> 5)] =
                    make_float2(p0, p1);
        }
    }
}

// ============ node GEMM (3-image smem, 2 blocks/SM) ==========
__global__ __launch_bounds__(256, 2) void gemm_node_mma(
        const float* __restrict__ bl, const float* __restrict__ br,
        const unsigned int* __restrict__ whiL, const unsigned int* __restrict__ wloL,
        const unsigned int* __restrict__ whiR, const unsigned int* __restrict__ wloR) {
    extern __shared__ __align__(16) unsigned int esm[];
    uint32_t sb = smem_u32(esm);
    int tid = threadIdx.x;
    int m0 = blockIdx.x * 128;

    const unsigned int* gWhi = blockIdx.y ? whiR : whiL;
    const unsigned int* gWlo = blockIdx.y ? wloR : wloL;
    const float* bias = blockIdx.y ? br : bl;
    float* C = blockIdx.y ? g_xr : g_xl;

    stage_all(sb, g_hhi, g_hlo, gWhi, m0, tid);
    cp_wait<0>();
    __syncthreads();

    int wid = tid >> 5, lane = tid & 31, g = lane >> 2, q = lane & 3;
    int mb = (wid & 3) * 32;
    int nb = (wid >> 2) * 64;

    float acc[2][8][4];
#pragma unroll
    for (int t = 0; t < 2; t++)
#pragma unroll
        for (int j = 0; j < 8; j++)
#pragma unroll
            for (int c = 0; c < 4; c++) acc[t][j][c] = 0.f;

    pass_mma(acc, sb + 2 * TB, sb, mb, nb, lane);   // (Alo, Whi)
    __syncthreads();
    stage_Wlo(sb + 2 * TB, gWlo, tid);              // Wlo -> Alo space
    pass_mma(acc, sb + TB, sb, mb, nb, lane);       // (Ahi, Whi)
    cp_wait<0>();
    __syncthreads();
    pass_mma(acc, sb + TB, sb + 2 * TB, mb, nb, lane); // (Ahi, Wlo)

    float2 biasv[8];
#pragma unroll
    for (int j = 0; j < 8; j++)
        biasv[j] = *(const float2*)&bias[nb + 8 * j + 2 * q];

#pragma unroll
    for (int t = 0; t < 2; t++) {
#pragma unroll
        for (int rr = 0; rr < 2; rr++) {
            int m = m0 + mb + 16 * t + 8 * rr + g;
            if (m < NN) {
#pragma unroll
                for (int j = 0; j < 8; j++) {
                    int cc = nb + 8 * j + 2 * q;
                    *(float2*)&C[(size_t)m * HID + cc] =
                        make_float2(acc[t][j][rr * 2 + 0] + biasv[j].x,
                                    acc[t][j][rr * 2 + 1] + biasv[j].y);
                }
            }
        }
    }
}

// ---------------- layer-0 node projection (K=12) ----------------
__global__ void node_proj12(const float* __restrict__ x,
                            const float* __restrict__ Wl, const float* __restrict__ bl,
                            const float* __restrict__ Wr, const float* __restrict__ br) {
    int idx = blockIdx.x * blockDim.x + threadIdx.x;
    int n = idx >> 7, j = idx & 127;
    float a = __ldg(&bl[j]);
    float b = __ldg(&br[j]);
#pragma unroll
    for (int k = 0; k < 12; k++) {
        float xv = __ldg(&x[n * 12 + k]);
        a = fmaf(xv, __ldg(&Wl[k * HID + j]), a);
        b = fmaf(xv, __ldg(&Wr[k * HID + j]), b);
    }
    g_xl[idx] = a;
    g_xr[idx] = b;
}

// ------- fused per-node: softmax + aggregate + bias + LN + SiLU (+res) ----------
template <bool RES, bool LAST>
__global__ void node_fused_kernel(const float* __restrict__ gat_bias,
                                  const float* __restrict__ lng,
                                  const float* __restrict__ lnb,
                                  float* __restrict__ dout) {
    int n = blockIdx.x * 4 + (threadIdx.x >> 5);
    int lane = threadIdx.x & 31;
    if (n >= NN) return;
    int s0 = g_rowptr[n];
    int s1 = g_rowptr[n + 1];

    float mx = -3.4e38f;
    for (int p = s0 * 4 + lane; p < s1 * 4; p += 32)
        mx = fmaxf(mx, g_score[p]);
    mx = fmaxf(mx, __shfl_xor_sync(0xffffffffu, mx, 4));
    mx = fmaxf(mx, __shfl_xor_sync(0xffffffffu, mx, 8));
    mx = fmaxf(mx, __shfl_xor_sync(0xffffffffu, mx, 16));

    float den = 0.f;
    for (int p = s0 * 4 + lane; p < s1 * 4; p += 32)
        den += __expf(g_score[p] - mx);
    den += __shfl_xor_sync(0xffffffffu, den, 4);
    den += __shfl_xor_sync(0xffffffffu, den, 8);
    den += __shfl_xor_sync(0xffffffffu, den, 16);
    float inv = __fdividef(1.f, den + 1e-16f);

    float acc0 = 0.f, acc1 = 0.f, acc2 = 0.f, acc3 = 0.f;
    for (int i = s0; i < s1; i++) {
        int src = g_sd[i].x;
        float a = 0.f;
        if (lane < 4) a = __expf(g_score[(size_t)i * 4 + lane] - mx) * inv;
        float al0 = __shfl_sync(0xffffffffu, a, 0);
        float al1 = __shfl_sync(0xffffffffu, a, 1);
        float al2 = __shfl_sync(0xffffffffu, a, 2);
        float al3 = __shfl_sync(0xffffffffu, a, 3);
        const float* xl = &g_xl[(size_t)src * HID];
        acc0 = fmaf(xl[0 * DH + lane], al0, acc0);
        acc1 = fmaf(xl[1 * DH + lane], al1, acc1);
        acc2 = fmaf(xl[2 * DH + lane], al2, acc2);
        acc3 = fmaf(xl[3 * DH + lane], al3, acc3);
    }

    float v0 = acc0 + __ldg(&gat_bias[0 * DH + lane]);
    float v1 = acc1 + __ldg(&gat_bias[1 * DH + lane]);
    float v2 = acc2 + __ldg(&gat_bias[2 * DH + lane]);
    float v3 = acc3 + __ldg(&gat_bias[3 * DH + lane]);

    float sm = v0 + v1 + v2 + v3;
#pragma unroll
    for (int off = 16; off; off >>= 1) sm += __shfl_xor_sync(0xffffffffu, sm, off);
    float mean = sm * (1.f / 128.f);
    float d0 = v0 - mean, d1 = v1 - mean, d2 = v2 - mean, d3 = v3 - mean;
    float sq = d0 * d0 + d1 * d1 + d2 * d2 + d3 * d3;
#pragma unroll
    for (int off = 16; off; off >>= 1) sq += __shfl_xor_sync(0xffffffffu, sq, off);
    float rstd = rsqrtf(sq * (1.f / 128.f) + 1e-5f);

#pragma unroll
    for (int h = 0; h < 4; h++) {
        int j = h * DH + lane;
        float d = (h == 0 ? d0 : h == 1 ? d1 : h == 2 ? d2 : d3);
        float t = fmaf(d * rstd, __ldg(&lng[j]), __ldg(&lnb[j]));
        float sil = fast_silu(t);
        float o = RES ? (g_h[n * HID + j] + sil) : sil;
        if (LAST) {
            dout[n * HID + j] = o;
        } else {
            g_h[n * HID + j] = o;
            float on = __shfl_down_sync(0xffffffffu, o, 1);
            if (!(lane & 1)) {
                float h0, l0, h1, l1;
                bf_split(o, h0, l0);
                bf_split(on, h1, l1);
                g_hhi[(size_t)n * 64 + (j >> 1)] = packbf2(h0, h1);
                g_hlo[(size_t)n * 64 + (j >> 1)] = packbf2(l0, l1);
            }
        }
    }
}

// ---------------- launch ----------------
extern "C" void kernel_launch(void* const* d_in, const int* in_sizes, int n_in,
                              void* d_out, int out_size) {
    const float* x     = (const float*)d_in[0];
    const int*   ei    = (const int*)  d_in[1];
    const float* eattr = (const float*)d_in[2];
    const float* epw   = (const float*)d_in[3];
    const float* epb   = (const float*)d_in[4];
    const float* l0Wl  = (const float*)d_in[5];
    const float* l0bl  = (const float*)d_in[6];
    const float* l0Wr  = (const float*)d_in[7];
    const float* l0br  = (const float*)d_in[8];
    const float* l0We  = (const float*)d_in[9];
    const float* l0att = (const float*)d_in[10];
    const float* l0bias= (const float*)d_in[11];
    const float* Wl    = (const float*)d_in[12];
    const float* bl    = (const float*)d_in[13];
    const float* Wr    = (const float*)d_in[14];
    const float* br    = (const float*)d_in[15];
    const float* We    = (const float*)d_in[16];
    const float* att   = (const float*)d_in[17];
    const float* bias  = (const float*)d_in[18];
    const float* lng   = (const float*)d_in[19];
    const float* lnb   = (const float*)d_in[20];
    float* out = (float*)d_out;

    static bool attr_set = false;
    if (!attr_set) {
        cudaFuncSetAttribute(gemm_edge_score_mma,
                             cudaFuncAttributeMaxDynamicSharedMemorySize, ESM_BYTES);
        cudaFuncSetAttribute(gemm_node_mma,
                             cudaFuncAttributeMaxDynamicSharedMemorySize, ESM_BYTES);
        attr_set = true;
    }

    unsigned int *dWhi, *dWlo;
    cudaGetSymbolAddress((void**)&dWhi, g_Wimg_hi);
    cudaGetSymbolAddress((void**)&dWlo, g_Wimg_lo);

    // CSR build (eproj needs g_pos)
    zero_kernel<<<(NN + 255) / 256, 256>>>();
    hist_kernel<<<(EE + 255) / 256, 256>>>(ei);
    deg_block_sum<<<NBLK, 1024>>>();
    bsum_scan<<<1, 128>>>();
    rowptr_kernel<<<NBLK, 1024>>>();
    scatter_kernel<<<(EE + 255) / 256, 256>>>(ei);

    // independent prep (all W images at once)
    eproj_kernel<<<(EE * 32) / 256, 256>>>(eattr, epw, epb);
    node_proj12<<<(NN * HID) / 256, 256>>>(x, l0Wl, l0bl, l0Wr, l0br);
    wprep_all<<<320, 256>>>(l0We, Wl, Wr, We);

    // layer 0
    gemm_edge_score_mma<<<EE / 128, 256, ESM_BYTES>>>(l0att, dWhi, dWlo);
    node_fused_kernel<false, false><<<NN / 4, 128>>>(l0bias, lng, lnb, nullptr);

    // layers 1..3 (residual)
    for (int i = 0; i < 3; i++) {
        int base = 1 + 3 * i;
        dim3 ng(NTILES, 2);
        gemm_node_mma<<<ng, 256, ESM_BYTES>>>(
            bl + i * HID, br + i * HID,
            dWhi + (size_t)(base + 0) * 8192, dWlo + (size_t)(base + 0) * 8192,
            dWhi + (size_t)(base + 1) * 8192, dWlo + (size_t)(base + 1) * 8192);
        gemm_edge_score_mma<<<EE / 128, 256, ESM_BYTES>>>(
            att + i * HID,
            dWhi + (size_t)(base + 2) * 8192, dWlo + (size_t)(base + 2) * 8192);
        if (i < 2)
            node_fused_kernel<true, false><<<NN / 4, 128>>>(
                bias + i * HID, lng + (i + 1) * HID, lnb + (i + 1) * HID, nullptr);
        else
            node_fused_kernel<true, true><<<NN / 4, 128>>>(
                bias + i * HID, lng + (i + 1) * HID, lnb + (i + 1) * HID, out);
    }
}